// round 9
// baseline (speedup 1.0000x reference)
#include <cuda_runtime.h>

#define HN 1024
#define WN 1024
#define NN (HN*WN)
#define TPB 512
#define NBLK (NN/TPB)   // 2048
#define STEPS 50

// ---- device-resident state (no allocations allowed) ----
__device__ float g_diag[NN], g_ce[NN], g_cw[NN], g_cs[NN], g_cn[NN];
__device__ float g_r[NN], g_pa[NN], g_pb[NN], g_Ap[NN];
__device__ float g_rs, g_alpha, g_beta;

// ---------------------------------------------------------------------------
// Exact emulation of XLA:CPU's strength-reduced dot: strict in-order scalar
// fp32 loop, separate rounded multiply and add (no FMA, no reassociation).
// Batched float4 loads give MLP for the serial FADD chain.
// ---------------------------------------------------------------------------
__device__ __forceinline__ float seq_dot(const float* __restrict__ a,
                                         const float* __restrict__ b) {
    const float4* __restrict__ a4 = (const float4*)a;
    const float4* __restrict__ b4 = (const float4*)b;
    float acc = 0.0f;
    for (int i = 0; i < NN / 4; i += 16) {
        float4 va[16], vb[16];
#pragma unroll
        for (int j = 0; j < 16; ++j) { va[j] = a4[i + j]; vb[j] = b4[i + j]; }
#pragma unroll
        for (int j = 0; j < 16; ++j) {
            acc = __fadd_rn(acc, __fmul_rn(va[j].x, vb[j].x));
            acc = __fadd_rn(acc, __fmul_rn(va[j].y, vb[j].y));
            acc = __fadd_rn(acc, __fmul_rn(va[j].z, vb[j].z));
            acc = __fadd_rn(acc, __fmul_rn(va[j].w, vb[j].w));
        }
    }
    return acc;
}

// ---------------------------------------------------------------------------
// init: zero stencil planes, r = p = b, x = 0
// ---------------------------------------------------------------------------
__global__ void init_kernel(const float* __restrict__ b, float* __restrict__ x) {
    int i = blockIdx.x * TPB + threadIdx.x;
    g_diag[i] = 0.f; g_ce[i] = 0.f; g_cw[i] = 0.f; g_cs[i] = 0.f; g_cn[i] = 0.f;
    float bv = b[i];
    g_r[i] = bv; g_pa[i] = bv; x[i] = 0.f;
}

// rs0 = <b,b> via the exact sequential fp32 chain; beta = 0
__global__ void init_scalars_kernel(const float* __restrict__ b) {
    g_rs = seq_dot(b, b);
    g_beta = 0.0f;
}

// ---------------------------------------------------------------------------
// scatter COO -> 5 stencil planes (each nnz targets a unique slot; no races)
// ---------------------------------------------------------------------------
__global__ void scatter_kernel(const int* __restrict__ rows,
                               const int* __restrict__ cols,
                               const float* __restrict__ vals, int nnz) {
    int k = blockIdx.x * blockDim.x + threadIdx.x;
    if (k >= nnz) return;
    int r = rows[k], c = cols[k];
    float v = vals[k];
    int d = c - r;
    if (d == 0)        g_diag[r] = v;
    else if (d == 1)   g_ce[r]   = v;
    else if (d == -1)  g_cw[r]   = v;
    else if (d == WN)  g_cs[r]   = v;
    else               g_cn[r]   = v;   // d == -WN
}

// ---------------------------------------------------------------------------
// fused: p_new = r + beta*p_old ; Ap = A*p_new
// Element-wise arithmetic mirrors the reference bit-for-bit:
//   - p update: t = fl(beta*p); p_new = fl(r + t)      (no FMA)
//   - SpMV: products fl(c*p) first, then sequential adds in row-sorted COO
//     order: E, W, S, N, diag
// flip selects p_old buffer (0: pa->pb, 1: pb->pa)
// ---------------------------------------------------------------------------
__device__ __forceinline__ float pnew_at(const float* __restrict__ pin,
                                         float beta, int j) {
    return __fadd_rn(g_r[j], __fmul_rn(beta, pin[j]));
}

__global__ void spmv_kernel(int flip) {
    const float* __restrict__ pin  = flip ? g_pb : g_pa;
    float*       __restrict__ pout = flip ? g_pa : g_pb;

    int i = blockIdx.x * TPB + threadIdx.x;
    float beta = g_beta;
    int xc = i & (WN - 1);

    float pn = pnew_at(pin, beta, i);

    float acc = 0.0f;
    if (xc < WN - 1) acc = __fadd_rn(acc, __fmul_rn(g_ce[i], pnew_at(pin, beta, i + 1)));
    if (xc > 0)      acc = __fadd_rn(acc, __fmul_rn(g_cw[i], pnew_at(pin, beta, i - 1)));
    if (i < NN - WN) acc = __fadd_rn(acc, __fmul_rn(g_cs[i], pnew_at(pin, beta, i + WN)));
    if (i >= WN)     acc = __fadd_rn(acc, __fmul_rn(g_cn[i], pnew_at(pin, beta, i - WN)));
    acc = __fadd_rn(acc, __fmul_rn(g_diag[i], pn));

    pout[i] = pn;
    g_Ap[i] = acc;
}

// alpha = rs / <p,Ap>_seq   (fp32 division, like the reference)
__global__ void dot_alpha_kernel(int flip) {
    const float* p = flip ? g_pa : g_pb;   // p_new written by spmv
    float pAp = seq_dot(p, g_Ap);
    g_alpha = __fdiv_rn(g_rs, pAp);
}

// ---------------------------------------------------------------------------
// fused: x += alpha*p ; r -= alpha*Ap   (strict no-FMA)
// flip matches the spmv that produced p (p lives in the *out* buffer)
// ---------------------------------------------------------------------------
__global__ void update_kernel(float* __restrict__ x, int flip) {
    const float* __restrict__ p = flip ? g_pa : g_pb;

    int i = blockIdx.x * TPB + threadIdx.x;
    float alpha = g_alpha;
    x[i] = __fadd_rn(x[i], __fmul_rn(alpha, p[i]));
    g_r[i] = __fsub_rn(g_r[i], __fmul_rn(alpha, g_Ap[i]));
}

// beta = rs_new / rs ; rs = rs_new   (fp32 division)
__global__ void dot_beta_kernel() {
    float rs_new = seq_dot(g_r, g_r);
    g_beta = __fdiv_rn(rs_new, g_rs);
    g_rs = rs_new;
}

// ---------------------------------------------------------------------------
extern "C" void kernel_launch(void* const* d_in, const int* in_sizes, int n_in,
                              void* d_out, int out_size) {
    const int*   rows = (const int*)d_in[0];
    const int*   cols = (const int*)d_in[1];
    const float* vals = (const float*)d_in[2];
    const float* b    = (const float*)d_in[3];
    float*       x    = (float*)d_out;
    int nnz = in_sizes[0];

    init_kernel<<<NBLK, TPB>>>(b, x);
    scatter_kernel<<<(nnz + 255) / 256, 256>>>(rows, cols, vals, nnz);
    init_scalars_kernel<<<1, 1>>>(b);

    for (int it = 0; it < STEPS; ++it) {
        int flip = it & 1;
        spmv_kernel<<<NBLK, TPB>>>(flip);
        dot_alpha_kernel<<<1, 1>>>(flip);
        update_kernel<<<NBLK, TPB>>>(x, flip);
        dot_beta_kernel<<<1, 1>>>();
    }
}

// round 10
// speedup vs baseline: 6.3716x; 6.3716x over previous
#include <cuda_runtime.h>

#define HN 1024
#define WN 1024
#define NN (HN*WN)
#define TPB 512
#define NBLK (NN/TPB)   // 2048
#define STEPS 50

#define DOT_TPB 1024
#define TILE_F  8192          // floats per smem tile (32KB)
#define NTILES  (NN/TILE_F)   // 128

// ---- device-resident state (no allocations allowed) ----
__device__ float g_diag[NN], g_ce[NN], g_cw[NN], g_cs[NN], g_cn[NN];
__device__ float g_r[NN], g_pa[NN], g_pb[NN], g_Ap[NN], g_t[NN];
__device__ float g_rs, g_alpha, g_beta;

// ---------------------------------------------------------------------------
// init: zero stencil planes, r = p = b, x = 0, t = rn(b*b)
// ---------------------------------------------------------------------------
__global__ void init_kernel(const float* __restrict__ b, float* __restrict__ x) {
    int i = blockIdx.x * TPB + threadIdx.x;
    g_diag[i] = 0.f; g_ce[i] = 0.f; g_cw[i] = 0.f; g_cs[i] = 0.f; g_cn[i] = 0.f;
    float bv = b[i];
    g_r[i] = bv; g_pa[i] = bv; x[i] = 0.f;
    g_t[i] = __fmul_rn(bv, bv);
}

// ---------------------------------------------------------------------------
// scatter COO -> 5 stencil planes (each nnz targets a unique slot; no races)
// ---------------------------------------------------------------------------
__global__ void scatter_kernel(const int* __restrict__ rows,
                               const int* __restrict__ cols,
                               const float* __restrict__ vals, int nnz) {
    int k = blockIdx.x * blockDim.x + threadIdx.x;
    if (k >= nnz) return;
    int r = rows[k], c = cols[k];
    float v = vals[k];
    int d = c - r;
    if (d == 0)        g_diag[r] = v;
    else if (d == 1)   g_ce[r]   = v;
    else if (d == -1)  g_cw[r]   = v;
    else if (d == WN)  g_cs[r]   = v;
    else               g_cn[r]   = v;   // d == -WN
}

// ---------------------------------------------------------------------------
// Serial fp32 chain over g_t, bit-identical to XLA:CPU's in-order scalar
// reduce: acc = rn(acc + t_k), k ascending, acc0 = 0.
// 1023 threads double-buffer 32KB tiles into smem; thread 0 runs the chain
// from smem with ping-pong register batches (32 floats each) so the 29-cyc
// LDS latency and all DRAM latency hide behind the 128-cyc FADD chain.
// mode 0: rs = acc, beta = 0          (init <b,b>)
// mode 1: alpha = rs / acc            (<p,Ap>)
// mode 2: beta = acc / rs, rs = acc   (<r,r>)
// ---------------------------------------------------------------------------
__device__ __forceinline__ void chain32(float& acc, const float4* s, int batch) {
    float4 v0 = s[batch*8+0], v1 = s[batch*8+1], v2 = s[batch*8+2], v3 = s[batch*8+3];
    float4 v4 = s[batch*8+4], v5 = s[batch*8+5], v6 = s[batch*8+6], v7 = s[batch*8+7];
    acc=__fadd_rn(acc,v0.x); acc=__fadd_rn(acc,v0.y); acc=__fadd_rn(acc,v0.z); acc=__fadd_rn(acc,v0.w);
    acc=__fadd_rn(acc,v1.x); acc=__fadd_rn(acc,v1.y); acc=__fadd_rn(acc,v1.z); acc=__fadd_rn(acc,v1.w);
    acc=__fadd_rn(acc,v2.x); acc=__fadd_rn(acc,v2.y); acc=__fadd_rn(acc,v2.z); acc=__fadd_rn(acc,v2.w);
    acc=__fadd_rn(acc,v3.x); acc=__fadd_rn(acc,v3.y); acc=__fadd_rn(acc,v3.z); acc=__fadd_rn(acc,v3.w);
    acc=__fadd_rn(acc,v4.x); acc=__fadd_rn(acc,v4.y); acc=__fadd_rn(acc,v4.z); acc=__fadd_rn(acc,v4.w);
    acc=__fadd_rn(acc,v5.x); acc=__fadd_rn(acc,v5.y); acc=__fadd_rn(acc,v5.z); acc=__fadd_rn(acc,v5.w);
    acc=__fadd_rn(acc,v6.x); acc=__fadd_rn(acc,v6.y); acc=__fadd_rn(acc,v6.z); acc=__fadd_rn(acc,v6.w);
    acc=__fadd_rn(acc,v7.x); acc=__fadd_rn(acc,v7.y); acc=__fadd_rn(acc,v7.z); acc=__fadd_rn(acc,v7.w);
}

__global__ void __launch_bounds__(DOT_TPB, 1) chain_kernel(int mode) {
    __shared__ float buf[2][TILE_F];
    int tid = threadIdx.x;

    // preload tile 0
    {
        const float4* src = (const float4*)g_t;
        float4* dst = (float4*)buf[0];
        for (int j = tid; j < TILE_F/4; j += DOT_TPB) dst[j] = src[j];
    }
    __syncthreads();

    float acc = 0.0f;
    for (int t = 0; t < NTILES; ++t) {
        int cur = t & 1;
        // prefetch next tile while thread 0 chains this one
        if (t + 1 < NTILES) {
            const float4* src = (const float4*)(g_t + (t + 1) * TILE_F);
            float4* dst = (float4*)buf[1 - cur];
            for (int j = tid; j < TILE_F/4; j += DOT_TPB) dst[j] = src[j];
        }
        if (tid == 0) {
            const float4* s = (const float4*)buf[cur];
            for (int i = 0; i < TILE_F/32; ++i)
                chain32(acc, s, i);
        }
        __syncthreads();
    }

    if (tid == 0) {
        if (mode == 0)      { g_rs = acc; g_beta = 0.0f; }
        else if (mode == 1) { g_alpha = __fdiv_rn(g_rs, acc); }
        else                { g_beta = __fdiv_rn(acc, g_rs); g_rs = acc; }
    }
}

// ---------------------------------------------------------------------------
// fused: p_new = r + beta*p_old ; Ap = A*p_new ; t = rn(p_new*Ap)
// Element-wise arithmetic mirrors the reference bit-for-bit:
//   - p update: t = fl(beta*p); p_new = fl(r + t)      (no FMA)
//   - SpMV: products fl(c*p) first, then sequential adds in row-sorted COO
//     order: E, W, S, N, diag
// flip selects p_old buffer (0: pa->pb, 1: pb->pa)
// ---------------------------------------------------------------------------
__device__ __forceinline__ float pnew_at(const float* __restrict__ pin,
                                         float beta, int j) {
    return __fadd_rn(g_r[j], __fmul_rn(beta, pin[j]));
}

__global__ void spmv_kernel(int flip) {
    const float* __restrict__ pin  = flip ? g_pb : g_pa;
    float*       __restrict__ pout = flip ? g_pa : g_pb;

    int i = blockIdx.x * TPB + threadIdx.x;
    float beta = g_beta;
    int xc = i & (WN - 1);

    float pn = pnew_at(pin, beta, i);

    float acc = 0.0f;
    if (xc < WN - 1) acc = __fadd_rn(acc, __fmul_rn(g_ce[i], pnew_at(pin, beta, i + 1)));
    if (xc > 0)      acc = __fadd_rn(acc, __fmul_rn(g_cw[i], pnew_at(pin, beta, i - 1)));
    if (i < NN - WN) acc = __fadd_rn(acc, __fmul_rn(g_cs[i], pnew_at(pin, beta, i + WN)));
    if (i >= WN)     acc = __fadd_rn(acc, __fmul_rn(g_cn[i], pnew_at(pin, beta, i - WN)));
    acc = __fadd_rn(acc, __fmul_rn(g_diag[i], pn));

    pout[i] = pn;
    g_Ap[i] = acc;
    g_t[i]  = __fmul_rn(pn, acc);
}

// ---------------------------------------------------------------------------
// fused: x += alpha*p ; r -= alpha*Ap ; t = rn(r*r)   (strict no-FMA)
// flip matches the spmv that produced p (p lives in the *out* buffer)
// ---------------------------------------------------------------------------
__global__ void update_kernel(float* __restrict__ x, int flip) {
    const float* __restrict__ p = flip ? g_pa : g_pb;

    int i = blockIdx.x * TPB + threadIdx.x;
    float alpha = g_alpha;
    x[i] = __fadd_rn(x[i], __fmul_rn(alpha, p[i]));
    float rv = __fsub_rn(g_r[i], __fmul_rn(alpha, g_Ap[i]));
    g_r[i] = rv;
    g_t[i] = __fmul_rn(rv, rv);
}

// ---------------------------------------------------------------------------
extern "C" void kernel_launch(void* const* d_in, const int* in_sizes, int n_in,
                              void* d_out, int out_size) {
    const int*   rows = (const int*)d_in[0];
    const int*   cols = (const int*)d_in[1];
    const float* vals = (const float*)d_in[2];
    const float* b    = (const float*)d_in[3];
    float*       x    = (float*)d_out;
    int nnz = in_sizes[0];

    init_kernel<<<NBLK, TPB>>>(b, x);
    scatter_kernel<<<(nnz + 255) / 256, 256>>>(rows, cols, vals, nnz);
    chain_kernel<<<1, DOT_TPB>>>(0);

    for (int it = 0; it < STEPS; ++it) {
        int flip = it & 1;
        spmv_kernel<<<NBLK, TPB>>>(flip);
        chain_kernel<<<1, DOT_TPB>>>(1);
        update_kernel<<<NBLK, TPB>>>(x, flip);
        chain_kernel<<<1, DOT_TPB>>>(2);
    }
}